// round 15
// baseline (speedup 1.0000x reference)
#include <cuda_runtime.h>
#include <cuda_fp16.h>
#include <cstdint>

// Problem constants
#define BB 32
#define CC 256
#define HH 32
#define WW 32
#define KK 1024
#define NN 1024                      // H*W
#define ZQ_SIZE (BB * CC * HH * WW)  // 8388608
#define IDX_SIZE (BB * NN)           // 32768

// ---------------- k_mma smem layout (u32 units) ----------------
#define OFF_AH 0
#define OFF_AL 16896
#define AL_B   67584                  // OFF_AL * 4 bytes
#define MT_B   8448                   // 16 rows * 132 u32 * 4 B
#define OFF_EB 33792
#define EWR_SEG 2560                  // per wr group (u32)
#define EBUF_SEG 1280                 // per buffer
#define ESPL_SEG 640                  // per split
#define OFF_E2 44032
#define SMEM_U32 45056
#define SMEM_MMA_BYTES (SMEM_U32 * 4)   // 180224

#define INV2048 4.8828125e-4f

// Device scratch (allocation-free rule: __device__ globals)
__device__ float g_zpt[BB * NN * CC];   // view rows: g_zpt[b][n][c'] fp32
__device__ float g_e2[KK];
__device__ float g_z2[BB * NN];         // view-column norms
__device__ int   g_idx[BB * NN];
__device__ float g_losspart[2048];
// pre-split fp16 operands
__device__ __align__(16) __half g_eh[KK * CC];          // E hi halves [k][c]
__device__ __align__(16) __half g_el[KK * CC];          // E lo halves
__device__ __align__(16) __half g_zh[BB * NN * CC];     // A hi halves [b][n][c] (view rows)
__device__ __align__(16) __half g_zl[BB * NN * CC];     // A lo halves

// ---------- helpers ----------
__device__ __forceinline__ __half lo_split(float x, __half h) {
    return __float2half_rn((x - __half2float(h)) * 2048.0f);
}
__device__ __forceinline__ uint32_t smem_u32(const void* p) {
    uint32_t a;
    asm("{ .reg .u64 t; cvta.to.shared.u64 t, %1; cvt.u32.u64 %0, t; }" : "=r"(a) : "l"(p));
    return a;
}
__device__ __forceinline__ void ldsm4(uint32_t* r, uint32_t addr) {
    asm volatile("ldmatrix.sync.aligned.m8n8.x4.shared.b16 {%0,%1,%2,%3}, [%4];"
                 : "=r"(r[0]), "=r"(r[1]), "=r"(r[2]), "=r"(r[3]) : "r"(addr));
}
__device__ __forceinline__ void mma_f16(float* d, const uint32_t* a,
                                        uint32_t b0, uint32_t b1) {
    asm volatile(
        "mma.sync.aligned.m16n8k16.row.col.f32.f16.f16.f32 "
        "{%0,%1,%2,%3}, {%4,%5,%6,%7}, {%8,%9}, {%0,%1,%2,%3};"
        : "+f"(d[0]), "+f"(d[1]), "+f"(d[2]), "+f"(d[3])
        : "r"(a[0]), "r"(a[1]), "r"(a[2]), "r"(a[3]), "r"(b0), "r"(b1));
}

// ---------- kernel 1: e2[k] + pre-split E halves ----------
__global__ void k_e2(const float* __restrict__ E) {
    int warp = threadIdx.x >> 5, lane = threadIdx.x & 31;
    int k = blockIdx.x * 8 + warp;
    const float* row = E + k * CC;
    float v[8];
    float s = 0.f;
#pragma unroll
    for (int i = 0; i < 8; i++) { v[i] = row[lane + 32 * i]; s = fmaf(v[i], v[i], s); }
#pragma unroll
    for (int o = 16; o; o >>= 1) s += __shfl_xor_sync(0xFFFFFFFFu, s, o);
    if (lane == 0) g_e2[k] = s;
#pragma unroll
    for (int i = 0; i < 8; i++) {
        int c = lane + 32 * i;
        __half hv = __float2half_rn(v[i]);
        g_eh[k * CC + c] = hv;
        g_el[k * CC + c] = lo_split(v[i], hv);
    }
}

// ---------- kernel 2: transpose z -> view rows (fp32 + fp16 halves) ----------
// A(n, 8h+r) = s[n & 255][r*4 + (n>>8)]
__global__ void k_tr(const float* __restrict__ z) {
    __shared__ float s[CC][33];
    int b = blockIdx.x >> 5, h = blockIdx.x & 31;
    int w = threadIdx.x & 31, t8 = threadIdx.x >> 5;
    const float* zp = z + ((long long)(b * CC) * HH + h) * WW + w;
#pragma unroll
    for (int i = 0; i < 32; i++) {
        int c = t8 * 32 + i;
        s[c][w] = zp[(long long)c * HH * WW];
    }
    __syncthreads();
    int tid = threadIdx.x;
#pragma unroll
    for (int i = 0; i < 4; i++) {
        int n = i * 256 + tid;
        __align__(16) float vv[8];
        __align__(16) __half hh[8], ll[8];
#pragma unroll
        for (int r = 0; r < 8; r++) {
            float v = s[tid][r * 4 + i];
            vv[r] = v;
            __half hv = __float2half_rn(v);
            hh[r] = hv;
            ll[r] = lo_split(v, hv);
        }
        long long off = ((long long)b * NN + n) * CC + h * 8;
        *(float4*)&g_zpt[off] = *(float4*)vv;
        *(float4*)&g_zpt[off + 4] = *(float4*)(vv + 4);
        *(uint4*)&g_zh[off] = *(uint4*)hh;
        *(uint4*)&g_zl[off] = *(uint4*)ll;
    }
}

// ---------- kernel 3: z2 = ascending-c' fmaf chain over contiguous view rows ----------
__global__ void k_z2() {
    int id = blockIdx.x * 256 + threadIdx.x;   // 128 blocks x 256 = 32768
    const float* base = g_zpt + (long long)id * CC;
    float s = 0.f;
#pragma unroll 8
    for (int c4 = 0; c4 < 64; c4++) {
        float4 v = *(const float4*)&base[c4 * 4];
        s = fmaf(v.x, v.x, s);
        s = fmaf(v.y, v.y, s);
        s = fmaf(v.z, v.z, s);
        s = fmaf(v.w, v.w, s);
    }
    g_z2[id] = s;
}

// ---------- kernel 4: fp16 2-split mma.sync + ldmatrix + argmin (R14 structure) ----------
__global__ void __launch_bounds__(512, 1) k_mma(float* __restrict__ dout, int out_size) {
    extern __shared__ uint32_t smu[];
    float* e2s = (float*)(smu + OFF_E2);
    uint32_t sb = smem_u32(smu);

    int tid = threadIdx.x;
    int w = tid >> 5, lane = tid & 31;
    int g = lane >> 2, t = lane & 3;
    int wr = w >> 2, wp = w & 3;
    int b = blockIdx.x >> 3;
    int n0 = (blockIdx.x & 7) * 128;

    // ---- A panel copy (128 rows, pre-split halves, padded rows) ----
    {
        const __half* zh = g_zh + ((long long)b * NN + n0) * CC;
        const __half* zl = g_zl + ((long long)b * NN + n0) * CC;
#pragma unroll
        for (int i = 0; i < 8; i++) {
            int unit = tid + 512 * i;
            int r = unit >> 5, j = unit & 31;
            *(uint4*)(smu + OFF_AH + r * 132 + j * 4) = *(const uint4*)(zh + r * 256 + j * 8);
            *(uint4*)(smu + OFF_AL + r * 132 + j * 4) = *(const uint4*)(zl + r * 256 + j * 8);
        }
    }
    for (int i = tid; i < KK; i += 512) e2s[i] = g_e2[i];

    // ---- E staging roles (group-local): tid_g in [0,128) ----
    int tid_g = tid & 127;
    int ekr = tid_g >> 2, eq = tid_g & 3;
    {
        const __half* eh = g_eh + (wr * 32 + ekr) * 256 + eq * 8;
        const __half* el = g_el + (wr * 32 + ekr) * 256 + eq * 8;
        uint32_t* dst = smu + OFF_EB + wr * EWR_SEG + ekr * 20 + eq * 4;
        *(uint4*)dst = *(const uint4*)eh;
        *(uint4*)(dst + ESPL_SEG) = *(const uint4*)el;
    }

    // ---- frag addresses (bytes) ----
    uint32_t a_row = (uint32_t)((wp * 32 + (lane & 15)) * 132 + (lane >> 4) * 4);
    uint32_t aaddr = sb + a_row * 4;
    uint32_t b_row = (uint32_t)(((lane & 7) + ((lane >> 4) & 1) * 8) * 20
                                + ((lane >> 3) & 1) * 4);

    float z2r[4], bv[4];
    int   bk[4];
#pragma unroll
    for (int mt = 0; mt < 2; mt++)
#pragma unroll
        for (int r8 = 0; r8 < 2; r8++) {
            z2r[mt * 2 + r8] = g_z2[b * NN + n0 + wp * 32 + mt * 16 + g + r8 * 8];
            bv[mt * 2 + r8] = 3.4e38f; bk[mt * 2 + r8] = 0;
        }
    __syncthreads();

    float acc_hh[8][4], acc_lo[8][4];
    uint4 ph, pl;

    for (int q = 0; q < 64; q++) {
        int buf = q & 1, ch = q & 7;
        if (ch == 0) {
#pragma unroll
            for (int f = 0; f < 8; f++)
#pragma unroll
                for (int j = 0; j < 4; j++) { acc_hh[f][j] = 0.f; acc_lo[f][j] = 0.f; }
        }
        if (q + 1 < 64) {
            int nk0 = ((q + 1) >> 3) * 128, nc0 = ((q + 1) & 7) * 32;
            const __half* eh = g_eh + (nk0 + wr * 32 + ekr) * 256 + nc0 + eq * 8;
            const __half* el = g_el + (nk0 + wr * 32 + ekr) * 256 + nc0 + eq * 8;
            ph = *(const uint4*)eh;
            pl = *(const uint4*)el;
        }

        uint32_t ebase = sb + (uint32_t)((OFF_EB + wr * EWR_SEG + buf * EBUF_SEG) * 4);
#pragma unroll
        for (int s = 0; s < 2; s++) {
            uint32_t co = (uint32_t)(ch * 64 + s * 32);
            uint32_t ah0[4], ah1[4], al0[4], al1[4];
            ldsm4(ah0, aaddr + co);
            ldsm4(ah1, aaddr + MT_B + co);
            ldsm4(al0, aaddr + AL_B + co);
            ldsm4(al1, aaddr + AL_B + MT_B + co);
#pragma unroll
            for (int np = 0; np < 2; np++) {
                uint32_t baddr = ebase + (b_row + np * 320) * 4 + s * 32;
                uint32_t bh[4], bl[4];
                ldsm4(bh, baddr);
                ldsm4(bl, baddr + ESPL_SEG * 4);
                int nf0 = np * 2, nf1 = nf0 + 1;
                mma_f16(acc_hh[nf0], ah0, bh[0], bh[1]);
                mma_f16(acc_hh[nf1], ah0, bh[2], bh[3]);
                mma_f16(acc_lo[nf0], ah0, bl[0], bl[1]);
                mma_f16(acc_lo[nf1], ah0, bl[2], bl[3]);
                mma_f16(acc_lo[nf0], al0, bh[0], bh[1]);
                mma_f16(acc_lo[nf1], al0, bh[2], bh[3]);
                mma_f16(acc_hh[4 + nf0], ah1, bh[0], bh[1]);
                mma_f16(acc_hh[4 + nf1], ah1, bh[2], bh[3]);
                mma_f16(acc_lo[4 + nf0], ah1, bl[0], bl[1]);
                mma_f16(acc_lo[4 + nf1], ah1, bl[2], bl[3]);
                mma_f16(acc_lo[4 + nf0], al1, bh[0], bh[1]);
                mma_f16(acc_lo[4 + nf1], al1, bh[2], bh[3]);
            }
        }

        if (ch == 7) {
            int k0 = (q >> 3) * 128;
#pragma unroll
            for (int mt = 0; mt < 2; mt++)
#pragma unroll
            for (int nf = 0; nf < 4; nf++) {
                int f = mt * 4 + nf;
                int ka = k0 + wr * 32 + nf * 8 + 2 * t;
                float e2a = e2s[ka], e2b = e2s[ka + 1];
                float dot0 = fmaf(acc_lo[f][0], INV2048, acc_hh[f][0]);
                float dot1 = fmaf(acc_lo[f][1], INV2048, acc_hh[f][1]);
                float dot2 = fmaf(acc_lo[f][2], INV2048, acc_hh[f][2]);
                float dot3 = fmaf(acc_lo[f][3], INV2048, acc_hh[f][3]);
                int ia = mt * 2, ib = mt * 2 + 1;
                float d0 = (e2a + z2r[ia]) - 2.0f * dot0;
                float d1 = (e2b + z2r[ia]) - 2.0f * dot1;
                float d2 = (e2a + z2r[ib]) - 2.0f * dot2;
                float d3 = (e2b + z2r[ib]) - 2.0f * dot3;
                if (d0 < bv[ia] || (d0 == bv[ia] && ka     < bk[ia])) { bv[ia] = d0; bk[ia] = ka; }
                if (d1 < bv[ia] || (d1 == bv[ia] && ka + 1 < bk[ia])) { bv[ia] = d1; bk[ia] = ka + 1; }
                if (d2 < bv[ib] || (d2 == bv[ib] && ka     < bk[ib])) { bv[ib] = d2; bk[ib] = ka; }
                if (d3 < bv[ib] || (d3 == bv[ib] && ka + 1 < bk[ib])) { bv[ib] = d3; bk[ib] = ka + 1; }
            }
        }

        if (q + 1 < 64) {
            uint32_t* dst = smu + OFF_EB + wr * EWR_SEG + (uint32_t)(buf ^ 1) * EBUF_SEG
                          + ekr * 20 + eq * 4;
            *(uint4*)dst = ph;
            *(uint4*)(dst + ESPL_SEG) = pl;
        }
        asm volatile("bar.sync %0, 128;" :: "r"(wr + 1) : "memory");
    }

#pragma unroll
    for (int i = 0; i < 4; i++) {
#pragma unroll
        for (int off = 1; off <= 2; off <<= 1) {
            float ov = __shfl_xor_sync(0xFFFFFFFFu, bv[i], off);
            int   ok = __shfl_xor_sync(0xFFFFFFFFu, bk[i], off);
            if (ov < bv[i] || (ov == bv[i] && ok < bk[i])) { bv[i] = ov; bk[i] = ok; }
        }
    }

    float* rval = (float*)smu;            // [4 wr][128 rows]
    int*   ridx = (int*)(smu + 512);
    __syncthreads();
    if (t == 0) {
#pragma unroll
        for (int mt = 0; mt < 2; mt++)
#pragma unroll
            for (int r8 = 0; r8 < 2; r8++) {
                int row = wp * 32 + mt * 16 + g + r8 * 8;
                rval[wr * 128 + row] = bv[mt * 2 + r8];
                ridx[wr * 128 + row] = bk[mt * 2 + r8];
            }
    }
    __syncthreads();
    if (tid < 128) {
        float bvv = rval[tid];
        int   bkk = ridx[tid];
#pragma unroll
        for (int r = 1; r < 4; r++) {
            float v = rval[r * 128 + tid];
            int   k2 = ridx[r * 128 + tid];
            if (v < bvv || (v == bvv && k2 < bkk)) { bvv = v; bkk = k2; }
        }
        int n = n0 + tid;
        g_idx[b * NN + n] = bkk;
        long long off = (long long)ZQ_SIZE + b * NN + n;
        if (off < (long long)out_size) dout[off] = (float)bkk;
    }
}

// ---------- kernel 5: gather z_q (STE-exact), loss partials, 2x c-split ----------
__global__ void k_gather(const float* __restrict__ z, const float* __restrict__ E,
                         float* __restrict__ dout) {
    __shared__ float srow[32 * 129];   // 32 rows x 128 c-half, pad 129
    __shared__ int   skid[32];
    __shared__ float sw[8];
    int b = blockIdx.x >> 6, h = (blockIdx.x >> 1) & 31, half = blockIdx.x & 1;
    int c0 = half * 128;
    int tid = threadIdx.x;
    int warp = tid >> 5, lane = tid & 31;

    if (tid < 32) skid[tid] = g_idx[b * NN + h * WW + tid];
    __syncthreads();

    // stage 32 E row-halves coalescedly: each warp loads 4 rows x 128 floats
#pragma unroll
    for (int r2 = 0; r2 < 4; r2++) {
        int r = warp * 4 + r2;
        const float* er = E + skid[r] * CC + c0;
#pragma unroll
        for (int i = 0; i < 4; i++)
            srow[r * 129 + lane + 32 * i] = er[lane + 32 * i];
    }
    __syncthreads();

    int w = lane;
    float local = 0.f;
#pragma unroll 4
    for (int s = 0; s < 16; s++) {
        int c = c0 + warp * 16 + s;
        long long zoff = ((long long)(b * CC + c) * HH + h) * WW + w;
        float zv = z[zoff];
        float eq = srow[w * 129 + warp * 16 + s];
        float d = eq - zv;
        local = fmaf(d, d, local);
        dout[zoff] = zv + (eq - zv);   // exact straight-through arithmetic
    }
#pragma unroll
    for (int o = 16; o; o >>= 1) local += __shfl_xor_sync(0xFFFFFFFFu, local, o);
    if (lane == 0) sw[warp] = local;
    __syncthreads();
    if (tid == 0) {
        float s2 = 0.f;
#pragma unroll
        for (int i = 0; i < 8; i++) s2 += sw[i];
        g_losspart[blockIdx.x] = s2;
    }
}

// ---------- kernel 6: deterministic loss finalize ----------
__global__ void k_final(float* __restrict__ dout, int out_size) {
    __shared__ float smf[256];
    float s = 0.f;
    for (int i = threadIdx.x; i < 2048; i += 256) s += g_losspart[i];
    smf[threadIdx.x] = s;
    __syncthreads();
    if (threadIdx.x == 0) {
        float t = 0.f;
        for (int i = 0; i < 256; i++) t += smf[i];
        float m = t / 8388608.0f;
        float loss = m + 0.25f * m;
        long long off = (long long)ZQ_SIZE + IDX_SIZE;
        if (off < (long long)out_size) dout[off] = loss;
    }
}

extern "C" void kernel_launch(void* const* d_in, const int* in_sizes, int n_in,
                              void* d_out, int out_size) {
    const float* z = (const float*)d_in[0];
    const float* E = (const float*)d_in[1];
    float* out = (float*)d_out;

    cudaFuncSetAttribute(k_mma, cudaFuncAttributeMaxDynamicSharedMemorySize, SMEM_MMA_BYTES);

    k_e2<<<128, 256>>>(E);
    k_tr<<<1024, 256>>>(z);
    k_z2<<<128, 256>>>();
    k_mma<<<256, 512, SMEM_MMA_BYTES>>>(out, out_size);
    if (out_size >= ZQ_SIZE) k_gather<<<2048, 256>>>(z, E, out);
    k_final<<<1, 256>>>(out, out_size);
}

// round 16
// speedup vs baseline: 1.0932x; 1.0932x over previous
#include <cuda_runtime.h>
#include <cuda_fp16.h>
#include <cstdint>

// Problem constants
#define BB 32
#define CC 256
#define HH 32
#define WW 32
#define KK 1024
#define NN 1024                      // H*W
#define ZP_BATCH (CC * NN)           // 262144 floats per batch
#define ZQ_SIZE (BB * CC * HH * WW)  // 8388608
#define IDX_SIZE (BB * NN)           // 32768

// ---------------- k_mma smem layout (u32 units) ----------------
#define OFF_AH 0
#define OFF_AL 16896
#define AL_B   67584                  // OFF_AL * 4 bytes
#define MT_B   8448                   // 16 rows * 132 u32 * 4 B
#define OFF_EB 33792
#define EWR_SEG 2560                  // per wr group (u32)
#define EBUF_SEG 1280                 // per buffer
#define ESPL_SEG 640                  // per split
#define OFF_E2 44032
#define SMEM_U32 45056
#define SMEM_MMA_BYTES (SMEM_U32 * 4)   // 180224

#define INV2048 4.8828125e-4f

// Device scratch (allocation-free rule: __device__ globals)
__device__ float g_zp[BB * ZP_BATCH];   // contiguous [b][h][w][c] image of z_p
__device__ float g_e2[KK];
__device__ float g_z2[BB * NN];         // view-column norms
__device__ int   g_idx[BB * NN];
__device__ float g_losspart[1024];
// pre-split fp16 operands
__device__ __align__(16) __half g_eh[KK * CC];          // E hi halves [k][c]
__device__ __align__(16) __half g_el[KK * CC];          // E lo halves
__device__ __align__(16) __half g_zh[BB * NN * CC];     // A hi halves [b][n][c] (view rows)
__device__ __align__(16) __half g_zl[BB * NN * CC];     // A lo halves

// ---------- helpers ----------
__device__ __forceinline__ __half lo_split(float x, __half h) {
    return __float2half_rn((x - __half2float(h)) * 2048.0f);
}
__device__ __forceinline__ uint32_t smem_u32(const void* p) {
    uint32_t a;
    asm("{ .reg .u64 t; cvta.to.shared.u64 t, %1; cvt.u32.u64 %0, t; }" : "=r"(a) : "l"(p));
    return a;
}
__device__ __forceinline__ void ldsm4(uint32_t* r, uint32_t addr) {
    asm volatile("ldmatrix.sync.aligned.m8n8.x4.shared.b16 {%0,%1,%2,%3}, [%4];"
                 : "=r"(r[0]), "=r"(r[1]), "=r"(r[2]), "=r"(r[3]) : "r"(addr));
}
__device__ __forceinline__ void mma_f16(float* d, const uint32_t* a,
                                        uint32_t b0, uint32_t b1) {
    asm volatile(
        "mma.sync.aligned.m16n8k16.row.col.f32.f16.f16.f32 "
        "{%0,%1,%2,%3}, {%4,%5,%6,%7}, {%8,%9}, {%0,%1,%2,%3};"
        : "+f"(d[0]), "+f"(d[1]), "+f"(d[2]), "+f"(d[3])
        : "r"(a[0]), "r"(a[1]), "r"(a[2]), "r"(a[3]), "r"(b0), "r"(b1));
}

// ---------- kernel 1: e2[k] + pre-split E halves ----------
__global__ void k_e2(const float* __restrict__ E) {
    int warp = threadIdx.x >> 5, lane = threadIdx.x & 31;
    int k = blockIdx.x * 8 + warp;
    const float* row = E + k * CC;
    float v[8];
    float s = 0.f;
#pragma unroll
    for (int i = 0; i < 8; i++) { v[i] = row[lane + 32 * i]; s = fmaf(v[i], v[i], s); }
#pragma unroll
    for (int o = 16; o; o >>= 1) s += __shfl_xor_sync(0xFFFFFFFFu, s, o);
    if (lane == 0) g_e2[k] = s;
#pragma unroll
    for (int i = 0; i < 8; i++) {
        int c = lane + 32 * i;
        __half hv = __float2half_rn(v[i]);
        g_eh[k * CC + c] = hv;
        g_el[k * CC + c] = lo_split(v[i], hv);
    }
}

// ---------- kernel 2: transpose z -> g_zp, and emit A-row halves ----------
__global__ void k_tr(const float* __restrict__ z) {
    __shared__ float s[CC][33];
    int b = blockIdx.x >> 5, h = blockIdx.x & 31;
    int w = threadIdx.x & 31, t8 = threadIdx.x >> 5;
    const float* zp = z + ((long long)(b * CC) * HH + h) * WW + w;
#pragma unroll
    for (int i = 0; i < 32; i++) {
        int c = t8 * 32 + i;
        s[c][w] = zp[(long long)c * HH * WW];
    }
    __syncthreads();
    float* out = g_zp + (long long)b * ZP_BATCH + h * (WW * CC);
#pragma unroll
    for (int i = 0; i < 32; i++) {
        int f = threadIdx.x + i * 256;
        int c = f & 255, ww = f >> 8;
        out[f] = s[c][ww];
    }
    // A(n, 8h+c') = flat[(8h+c')*1024 + n] = s[n & 255][c'*4 + (n>>8)]
    int tid = threadIdx.x;
#pragma unroll
    for (int i = 0; i < 4; i++) {
        int n = i * 256 + tid;
        __align__(16) __half hh[8], ll[8];
#pragma unroll
        for (int cp = 0; cp < 8; cp++) {
            float v = s[tid][cp * 4 + i];
            __half hv = __float2half_rn(v);
            hh[cp] = hv;
            ll[cp] = lo_split(v, hv);
        }
        long long off = ((long long)b * NN + n) * CC + h * 8;
        *(uint4*)&g_zh[off] = *(uint4*)hh;
        *(uint4*)&g_zl[off] = *(uint4*)ll;
    }
}

// ---------- kernel 3: z2[b][n] over the REINTERPRETED [256,1024] view ----------
// Identical ascending-i fmaf chain; loads batched 16-wide for MLP.
__global__ void k_z2() {
    int b = blockIdx.x >> 2;
    int n = (blockIdx.x & 3) * 256 + threadIdx.x;
    const float* base = g_zp + (long long)b * ZP_BATCH + n;
    float s = 0.f;
    for (int i0 = 0; i0 < CC; i0 += 16) {
        float r[16];
#pragma unroll
        for (int j = 0; j < 16; j++) r[j] = base[(i0 + j) * NN];
#pragma unroll
        for (int j = 0; j < 16; j++) s = fmaf(r[j], r[j], s);
    }
    g_z2[b * NN + n] = s;
}

// ---------- kernel 4: fp16 2-split mma.sync + ldmatrix + argmin (R14 structure) ----------
// 512 thr. Warp w: wp = w&3 (rows [wp*32,+32)), wr = w>>2 (codes [wr*32,+32) per slab).
// wr-groups sync on named barrier wr+1 -> independent pipelines overlap LDSM with HMMA.
__global__ void __launch_bounds__(512, 1) k_mma(float* __restrict__ dout, int out_size) {
    extern __shared__ uint32_t smu[];
    float* e2s = (float*)(smu + OFF_E2);
    uint32_t sb = smem_u32(smu);

    int tid = threadIdx.x;
    int w = tid >> 5, lane = tid & 31;
    int g = lane >> 2, t = lane & 3;
    int wr = w >> 2, wp = w & 3;
    int b = blockIdx.x >> 3;
    int n0 = (blockIdx.x & 7) * 128;

    // ---- A panel copy (128 rows, pre-split halves, padded rows) ----
    {
        const __half* zh = g_zh + ((long long)b * NN + n0) * CC;
        const __half* zl = g_zl + ((long long)b * NN + n0) * CC;
#pragma unroll
        for (int i = 0; i < 8; i++) {
            int unit = tid + 512 * i;
            int r = unit >> 5, j = unit & 31;
            *(uint4*)(smu + OFF_AH + r * 132 + j * 4) = *(const uint4*)(zh + r * 256 + j * 8);
            *(uint4*)(smu + OFF_AL + r * 132 + j * 4) = *(const uint4*)(zl + r * 256 + j * 8);
        }
    }
    for (int i = tid; i < KK; i += 512) e2s[i] = g_e2[i];

    // ---- E staging roles (group-local): tid_g in [0,128) ----
    int tid_g = tid & 127;
    int ekr = tid_g >> 2, eq = tid_g & 3;
    {
        const __half* eh = g_eh + (wr * 32 + ekr) * 256 + eq * 8;
        const __half* el = g_el + (wr * 32 + ekr) * 256 + eq * 8;
        uint32_t* dst = smu + OFF_EB + wr * EWR_SEG + ekr * 20 + eq * 4;
        *(uint4*)dst = *(const uint4*)eh;
        *(uint4*)(dst + ESPL_SEG) = *(const uint4*)el;
    }

    // ---- frag addresses (bytes) ----
    uint32_t a_row = (uint32_t)((wp * 32 + (lane & 15)) * 132 + (lane >> 4) * 4);
    uint32_t aaddr = sb + a_row * 4;
    uint32_t b_row = (uint32_t)(((lane & 7) + ((lane >> 4) & 1) * 8) * 20
                                + ((lane >> 3) & 1) * 4);

    float z2r[4], bv[4];
    int   bk[4];
#pragma unroll
    for (int mt = 0; mt < 2; mt++)
#pragma unroll
        for (int r8 = 0; r8 < 2; r8++) {
            z2r[mt * 2 + r8] = g_z2[b * NN + n0 + wp * 32 + mt * 16 + g + r8 * 8];
            bv[mt * 2 + r8] = 3.4e38f; bk[mt * 2 + r8] = 0;
        }
    __syncthreads();

    float acc_hh[8][4], acc_lo[8][4];
    uint4 ph, pl;

    for (int q = 0; q < 64; q++) {
        int buf = q & 1, ch = q & 7;
        if (ch == 0) {
#pragma unroll
            for (int f = 0; f < 8; f++)
#pragma unroll
                for (int j = 0; j < 4; j++) { acc_hh[f][j] = 0.f; acc_lo[f][j] = 0.f; }
        }
        if (q + 1 < 64) {
            int nk0 = ((q + 1) >> 3) * 128, nc0 = ((q + 1) & 7) * 32;
            const __half* eh = g_eh + (nk0 + wr * 32 + ekr) * 256 + nc0 + eq * 8;
            const __half* el = g_el + (nk0 + wr * 32 + ekr) * 256 + nc0 + eq * 8;
            ph = *(const uint4*)eh;
            pl = *(const uint4*)el;
        }

        uint32_t ebase = sb + (uint32_t)((OFF_EB + wr * EWR_SEG + buf * EBUF_SEG) * 4);
#pragma unroll
        for (int s = 0; s < 2; s++) {
            uint32_t co = (uint32_t)(ch * 64 + s * 32);
            uint32_t ah0[4], ah1[4], al0[4], al1[4];
            ldsm4(ah0, aaddr + co);
            ldsm4(ah1, aaddr + MT_B + co);
            ldsm4(al0, aaddr + AL_B + co);
            ldsm4(al1, aaddr + AL_B + MT_B + co);
#pragma unroll
            for (int np = 0; np < 2; np++) {
                uint32_t baddr = ebase + (b_row + np * 320) * 4 + s * 32;
                uint32_t bh[4], bl[4];
                ldsm4(bh, baddr);
                ldsm4(bl, baddr + ESPL_SEG * 4);
                int nf0 = np * 2, nf1 = nf0 + 1;
                mma_f16(acc_hh[nf0], ah0, bh[0], bh[1]);
                mma_f16(acc_hh[nf1], ah0, bh[2], bh[3]);
                mma_f16(acc_lo[nf0], ah0, bl[0], bl[1]);
                mma_f16(acc_lo[nf1], ah0, bl[2], bl[3]);
                mma_f16(acc_lo[nf0], al0, bh[0], bh[1]);
                mma_f16(acc_lo[nf1], al0, bh[2], bh[3]);
                mma_f16(acc_hh[4 + nf0], ah1, bh[0], bh[1]);
                mma_f16(acc_hh[4 + nf1], ah1, bh[2], bh[3]);
                mma_f16(acc_lo[4 + nf0], ah1, bl[0], bl[1]);
                mma_f16(acc_lo[4 + nf1], ah1, bl[2], bl[3]);
                mma_f16(acc_lo[4 + nf0], al1, bh[0], bh[1]);
                mma_f16(acc_lo[4 + nf1], al1, bh[2], bh[3]);
            }
        }

        if (ch == 7) {
            int k0 = (q >> 3) * 128;
#pragma unroll
            for (int mt = 0; mt < 2; mt++)
#pragma unroll
            for (int nf = 0; nf < 4; nf++) {
                int f = mt * 4 + nf;
                int ka = k0 + wr * 32 + nf * 8 + 2 * t;
                float e2a = e2s[ka], e2b = e2s[ka + 1];
                float dot0 = fmaf(acc_lo[f][0], INV2048, acc_hh[f][0]);
                float dot1 = fmaf(acc_lo[f][1], INV2048, acc_hh[f][1]);
                float dot2 = fmaf(acc_lo[f][2], INV2048, acc_hh[f][2]);
                float dot3 = fmaf(acc_lo[f][3], INV2048, acc_hh[f][3]);
                int ia = mt * 2, ib = mt * 2 + 1;
                float d0 = (e2a + z2r[ia]) - 2.0f * dot0;
                float d1 = (e2b + z2r[ia]) - 2.0f * dot1;
                float d2 = (e2a + z2r[ib]) - 2.0f * dot2;
                float d3 = (e2b + z2r[ib]) - 2.0f * dot3;
                if (d0 < bv[ia] || (d0 == bv[ia] && ka     < bk[ia])) { bv[ia] = d0; bk[ia] = ka; }
                if (d1 < bv[ia] || (d1 == bv[ia] && ka + 1 < bk[ia])) { bv[ia] = d1; bk[ia] = ka + 1; }
                if (d2 < bv[ib] || (d2 == bv[ib] && ka     < bk[ib])) { bv[ib] = d2; bk[ib] = ka; }
                if (d3 < bv[ib] || (d3 == bv[ib] && ka + 1 < bk[ib])) { bv[ib] = d3; bk[ib] = ka + 1; }
            }
        }

        if (q + 1 < 64) {
            uint32_t* dst = smu + OFF_EB + wr * EWR_SEG + (uint32_t)(buf ^ 1) * EBUF_SEG
                          + ekr * 20 + eq * 4;
            *(uint4*)dst = ph;
            *(uint4*)(dst + ESPL_SEG) = pl;
        }
        asm volatile("bar.sync %0, 128;" :: "r"(wr + 1) : "memory");
    }

#pragma unroll
    for (int i = 0; i < 4; i++) {
#pragma unroll
        for (int off = 1; off <= 2; off <<= 1) {
            float ov = __shfl_xor_sync(0xFFFFFFFFu, bv[i], off);
            int   ok = __shfl_xor_sync(0xFFFFFFFFu, bk[i], off);
            if (ov < bv[i] || (ov == bv[i] && ok < bk[i])) { bv[i] = ov; bk[i] = ok; }
        }
    }

    float* rval = (float*)smu;            // [4 wr][128 rows]
    int*   ridx = (int*)(smu + 512);
    __syncthreads();
    if (t == 0) {
#pragma unroll
        for (int mt = 0; mt < 2; mt++)
#pragma unroll
            for (int r8 = 0; r8 < 2; r8++) {
                int row = wp * 32 + mt * 16 + g + r8 * 8;
                rval[wr * 128 + row] = bv[mt * 2 + r8];
                ridx[wr * 128 + row] = bk[mt * 2 + r8];
            }
    }
    __syncthreads();
    if (tid < 128) {
        float bvv = rval[tid];
        int   bkk = ridx[tid];
#pragma unroll
        for (int r = 1; r < 4; r++) {
            float v = rval[r * 128 + tid];
            int   k2 = ridx[r * 128 + tid];
            if (v < bvv || (v == bvv && k2 < bkk)) { bvv = v; bkk = k2; }
        }
        int n = n0 + tid;
        g_idx[b * NN + n] = bkk;
        long long off = (long long)ZQ_SIZE + b * NN + n;
        if (off < (long long)out_size) dout[off] = (float)bkk;
    }
}

// ---------- kernel 5: gather z_q (STE-exact), loss partials ----------
__global__ void k_gather(const float* __restrict__ z, const float* __restrict__ E,
                         float* __restrict__ dout) {
    __shared__ float srow[32 * 257];
    __shared__ int   skid[32];
    __shared__ float sw[8];
    int b = blockIdx.x >> 5, h = blockIdx.x & 31;
    int tid = threadIdx.x;
    int warp = tid >> 5, lane = tid & 31;

    if (tid < 32) skid[tid] = g_idx[b * NN + h * WW + tid];
    __syncthreads();

#pragma unroll
    for (int r2 = 0; r2 < 4; r2++) {
        int r = warp * 4 + r2;
        const float* er = E + skid[r] * CC;
#pragma unroll
        for (int i = 0; i < 8; i++)
            srow[r * 257 + lane + 32 * i] = er[lane + 32 * i];
    }
    __syncthreads();

    int w = lane;
    float local = 0.f;
#pragma unroll 4
    for (int s = 0; s < 32; s++) {
        int c = warp * 32 + s;
        long long zoff = ((long long)(b * CC + c) * HH + h) * WW + w;
        float zv = z[zoff];
        float eq = srow[w * 257 + c];
        float d = eq - zv;
        local = fmaf(d, d, local);
        dout[zoff] = zv + (eq - zv);   // exact straight-through arithmetic
    }
#pragma unroll
    for (int o = 16; o; o >>= 1) local += __shfl_xor_sync(0xFFFFFFFFu, local, o);
    if (lane == 0) sw[warp] = local;
    __syncthreads();
    if (tid == 0) {
        float s2 = 0.f;
#pragma unroll
        for (int i = 0; i < 8; i++) s2 += sw[i];
        g_losspart[blockIdx.x] = s2;
    }
}

// ---------- kernel 6: deterministic loss finalize ----------
__global__ void k_final(float* __restrict__ dout, int out_size) {
    __shared__ float smf[256];
    float s = 0.f;
    for (int i = threadIdx.x; i < 1024; i += 256) s += g_losspart[i];
    smf[threadIdx.x] = s;
    __syncthreads();
    if (threadIdx.x == 0) {
        float t = 0.f;
        for (int i = 0; i < 256; i++) t += smf[i];
        float m = t / 8388608.0f;
        float loss = m + 0.25f * m;
        long long off = (long long)ZQ_SIZE + IDX_SIZE;
        if (off < (long long)out_size) dout[off] = loss;
    }
}

extern "C" void kernel_launch(void* const* d_in, const int* in_sizes, int n_in,
                              void* d_out, int out_size) {
    const float* z = (const float*)d_in[0];
    const float* E = (const float*)d_in[1];
    float* out = (float*)d_out;

    cudaFuncSetAttribute(k_mma, cudaFuncAttributeMaxDynamicSharedMemorySize, SMEM_MMA_BYTES);

    k_e2<<<128, 256>>>(E);
    k_tr<<<1024, 256>>>(z);
    k_z2<<<128, 256>>>();
    k_mma<<<256, 512, SMEM_MMA_BYTES>>>(out, out_size);
    if (out_size >= ZQ_SIZE) k_gather<<<1024, 256>>>(z, E, out);
    k_final<<<1, 256>>>(out, out_size);
}

// round 17
// speedup vs baseline: 1.1163x; 1.0211x over previous
#include <cuda_runtime.h>
#include <cuda_fp16.h>
#include <cstdint>

// Problem constants
#define BB 32
#define CC 256
#define HH 32
#define WW 32
#define KK 1024
#define NN 1024                      // H*W
#define ZP_BATCH (CC * NN)           // 262144 floats per batch
#define ZQ_SIZE (BB * CC * HH * WW)  // 8388608
#define IDX_SIZE (BB * NN)           // 32768

// ---------------- k_mma smem layout (u32 units) ----------------
#define OFF_AH 0
#define OFF_AL 16896
#define AL_B   67584                  // OFF_AL * 4 bytes
#define MT_B   8448                   // 16 rows * 132 u32 * 4 B
#define OFF_EB 33792
#define EWR_SEG 2560                  // per wr group (u32)
#define EBUF_SEG 1280                 // per buffer
#define ESPL_SEG 640                  // per split
#define OFF_E2 44032
#define SMEM_U32 45056
#define SMEM_MMA_BYTES (SMEM_U32 * 4)   // 180224

#define INV2048 4.8828125e-4f

// Device scratch (allocation-free rule: __device__ globals)
__device__ float g_zp[BB * ZP_BATCH];   // contiguous [b][h][w][c] image of z_p
__device__ float g_e2[KK];
__device__ float g_z2[BB * NN];         // view-column norms
__device__ int   g_idx[BB * NN];
__device__ float g_losspart[1024];
// pre-split fp16 operands
__device__ __align__(16) __half g_eh[KK * CC];          // E hi halves [k][c]
__device__ __align__(16) __half g_el[KK * CC];          // E lo halves
__device__ __align__(16) __half g_zh[BB * NN * CC];     // A hi halves [b][n][c] (view rows)
__device__ __align__(16) __half g_zl[BB * NN * CC];     // A lo halves

// ---------- helpers ----------
__device__ __forceinline__ __half lo_split(float x, __half h) {
    return __float2half_rn((x - __half2float(h)) * 2048.0f);
}
__device__ __forceinline__ uint32_t smem_u32(const void* p) {
    uint32_t a;
    asm("{ .reg .u64 t; cvta.to.shared.u64 t, %1; cvt.u32.u64 %0, t; }" : "=r"(a) : "l"(p));
    return a;
}
__device__ __forceinline__ void ldsm4(uint32_t* r, uint32_t addr) {
    asm volatile("ldmatrix.sync.aligned.m8n8.x4.shared.b16 {%0,%1,%2,%3}, [%4];"
                 : "=r"(r[0]), "=r"(r[1]), "=r"(r[2]), "=r"(r[3]) : "r"(addr));
}
__device__ __forceinline__ void mma_f16(float* d, const uint32_t* a,
                                        uint32_t b0, uint32_t b1) {
    asm volatile(
        "mma.sync.aligned.m16n8k16.row.col.f32.f16.f16.f32 "
        "{%0,%1,%2,%3}, {%4,%5,%6,%7}, {%8,%9}, {%0,%1,%2,%3};"
        : "+f"(d[0]), "+f"(d[1]), "+f"(d[2]), "+f"(d[3])
        : "r"(a[0]), "r"(a[1]), "r"(a[2]), "r"(a[3]), "r"(b0), "r"(b1));
}
__device__ __forceinline__ void cp16(uint32_t dst, const void* src) {
    asm volatile("cp.async.cg.shared.global [%0], [%1], 16;" :: "r"(dst), "l"(src) : "memory");
}
__device__ __forceinline__ void cp_commit() {
    asm volatile("cp.async.commit_group;" ::: "memory");
}
__device__ __forceinline__ void cp_wait0() {
    asm volatile("cp.async.wait_group 0;" ::: "memory");
}

// ---------- kernel 1: e2[k] + pre-split E halves ----------
__global__ void k_e2(const float* __restrict__ E) {
    int warp = threadIdx.x >> 5, lane = threadIdx.x & 31;
    int k = blockIdx.x * 8 + warp;
    const float* row = E + k * CC;
    float v[8];
    float s = 0.f;
#pragma unroll
    for (int i = 0; i < 8; i++) { v[i] = row[lane + 32 * i]; s = fmaf(v[i], v[i], s); }
#pragma unroll
    for (int o = 16; o; o >>= 1) s += __shfl_xor_sync(0xFFFFFFFFu, s, o);
    if (lane == 0) g_e2[k] = s;
#pragma unroll
    for (int i = 0; i < 8; i++) {
        int c = lane + 32 * i;
        __half hv = __float2half_rn(v[i]);
        g_eh[k * CC + c] = hv;
        g_el[k * CC + c] = lo_split(v[i], hv);
    }
}

// ---------- kernel 2: transpose z -> g_zp, and emit A-row halves ----------
__global__ void k_tr(const float* __restrict__ z) {
    __shared__ float s[CC][33];
    int b = blockIdx.x >> 5, h = blockIdx.x & 31;
    int w = threadIdx.x & 31, t8 = threadIdx.x >> 5;
    const float* zp = z + ((long long)(b * CC) * HH + h) * WW + w;
#pragma unroll
    for (int i = 0; i < 32; i++) {
        int c = t8 * 32 + i;
        s[c][w] = zp[(long long)c * HH * WW];
    }
    __syncthreads();
    float* out = g_zp + (long long)b * ZP_BATCH + h * (WW * CC);
#pragma unroll
    for (int i = 0; i < 32; i++) {
        int f = threadIdx.x + i * 256;
        int c = f & 255, ww = f >> 8;
        out[f] = s[c][ww];
    }
    // A(n, 8h+c') = flat[(8h+c')*1024 + n] = s[n & 255][c'*4 + (n>>8)]
    int tid = threadIdx.x;
#pragma unroll
    for (int i = 0; i < 4; i++) {
        int n = i * 256 + tid;
        __align__(16) __half hh[8], ll[8];
#pragma unroll
        for (int cp = 0; cp < 8; cp++) {
            float v = s[tid][cp * 4 + i];
            __half hv = __float2half_rn(v);
            hh[cp] = hv;
            ll[cp] = lo_split(v, hv);
        }
        long long off = ((long long)b * NN + n) * CC + h * 8;
        *(uint4*)&g_zh[off] = *(uint4*)hh;
        *(uint4*)&g_zl[off] = *(uint4*)ll;
    }
}

// ---------- kernel 3: z2[b][n] over the REINTERPRETED [256,1024] view ----------
// Identical ascending-i fmaf chain; loads batched 16-wide for MLP.
__global__ void k_z2() {
    int b = blockIdx.x >> 2;
    int n = (blockIdx.x & 3) * 256 + threadIdx.x;
    const float* base = g_zp + (long long)b * ZP_BATCH + n;
    float s = 0.f;
    for (int i0 = 0; i0 < CC; i0 += 16) {
        float r[16];
#pragma unroll
        for (int j = 0; j < 16; j++) r[j] = base[(i0 + j) * NN];
#pragma unroll
        for (int j = 0; j < 16; j++) s = fmaf(r[j], r[j], s);
    }
    g_z2[b * NN + n] = s;
}

// ---------- kernel 4: fp16 2-split mma.sync + ldmatrix + argmin ----------
// 512 thr. Warp w: wp = w&3 (rows [wp*32,+32)), wr = w>>2 (codes [wr*32,+32) per slab).
// wr-groups sync on named barrier wr+1; E staged via cp.async (no register roundtrip).
__global__ void __launch_bounds__(512, 1) k_mma(float* __restrict__ dout, int out_size) {
    extern __shared__ uint32_t smu[];
    float* e2s = (float*)(smu + OFF_E2);
    uint32_t sb = smem_u32(smu);

    int tid = threadIdx.x;
    int w = tid >> 5, lane = tid & 31;
    int g = lane >> 2, t = lane & 3;
    int wr = w >> 2, wp = w & 3;
    int b = blockIdx.x >> 3;
    int n0 = (blockIdx.x & 7) * 128;

    // ---- A panel copy via cp.async (128 rows, pre-split halves, padded rows) ----
    {
        const __half* zh = g_zh + ((long long)b * NN + n0) * CC;
        const __half* zl = g_zl + ((long long)b * NN + n0) * CC;
#pragma unroll
        for (int i = 0; i < 8; i++) {
            int unit = tid + 512 * i;
            int r = unit >> 5, j = unit & 31;
            cp16(sb + (uint32_t)(OFF_AH + r * 132 + j * 4) * 4, zh + r * 256 + j * 8);
            cp16(sb + (uint32_t)(OFF_AL + r * 132 + j * 4) * 4, zl + r * 256 + j * 8);
        }
    }
    for (int i = tid; i < KK; i += 512) e2s[i] = g_e2[i];

    // ---- E staging roles (group-local): tid_g in [0,128) ----
    int tid_g = tid & 127;
    int ekr = tid_g >> 2, eq = tid_g & 3;
    uint32_t edst0 = sb + (uint32_t)(OFF_EB + wr * EWR_SEG + ekr * 20 + eq * 4) * 4;
    {
        const __half* eh = g_eh + (wr * 32 + ekr) * 256 + eq * 8;
        const __half* el = g_el + (wr * 32 + ekr) * 256 + eq * 8;
        cp16(edst0, eh);
        cp16(edst0 + ESPL_SEG * 4, el);
    }
    cp_commit();

    // ---- frag addresses (bytes) ----
    uint32_t a_row = (uint32_t)((wp * 32 + (lane & 15)) * 132 + (lane >> 4) * 4);
    uint32_t aaddr = sb + a_row * 4;
    uint32_t b_row = (uint32_t)(((lane & 7) + ((lane >> 4) & 1) * 8) * 20
                                + ((lane >> 3) & 1) * 4);

    float z2r[4], bv[4];
    int   bk[4];
#pragma unroll
    for (int mt = 0; mt < 2; mt++)
#pragma unroll
        for (int r8 = 0; r8 < 2; r8++) {
            z2r[mt * 2 + r8] = g_z2[b * NN + n0 + wp * 32 + mt * 16 + g + r8 * 8];
            bv[mt * 2 + r8] = 3.4e38f; bk[mt * 2 + r8] = 0;
        }
    cp_wait0();
    __syncthreads();

    float acc_hh[8][4], acc_lo[8][4];

    for (int q = 0; q < 64; q++) {
        int buf = q & 1, ch = q & 7;
        if (ch == 0) {
#pragma unroll
            for (int f = 0; f < 8; f++)
#pragma unroll
                for (int j = 0; j < 4; j++) { acc_hh[f][j] = 0.f; acc_lo[f][j] = 0.f; }
        }
        if (q + 1 < 64) {                      // async-prefetch next chunk into other buffer
            int nk0 = ((q + 1) >> 3) * 128, nc0 = ((q + 1) & 7) * 32;
            const __half* eh = g_eh + (nk0 + wr * 32 + ekr) * 256 + nc0 + eq * 8;
            const __half* el = g_el + (nk0 + wr * 32 + ekr) * 256 + nc0 + eq * 8;
            uint32_t dst = edst0 + (uint32_t)((buf ^ 1) * EBUF_SEG) * 4;
            cp16(dst, eh);
            cp16(dst + ESPL_SEG * 4, el);
            cp_commit();
        }

        uint32_t ebase = sb + (uint32_t)((OFF_EB + wr * EWR_SEG + buf * EBUF_SEG) * 4);
#pragma unroll
        for (int s = 0; s < 2; s++) {
            uint32_t co = (uint32_t)(ch * 64 + s * 32);
            uint32_t ah0[4], ah1[4], al0[4], al1[4];
            ldsm4(ah0, aaddr + co);
            ldsm4(ah1, aaddr + MT_B + co);
            ldsm4(al0, aaddr + AL_B + co);
            ldsm4(al1, aaddr + AL_B + MT_B + co);
#pragma unroll
            for (int np = 0; np < 2; np++) {
                uint32_t baddr = ebase + (b_row + np * 320) * 4 + s * 32;
                uint32_t bh[4], bl[4];
                ldsm4(bh, baddr);
                ldsm4(bl, baddr + ESPL_SEG * 4);
                int nf0 = np * 2, nf1 = nf0 + 1;
                mma_f16(acc_hh[nf0], ah0, bh[0], bh[1]);
                mma_f16(acc_hh[nf1], ah0, bh[2], bh[3]);
                mma_f16(acc_lo[nf0], ah0, bl[0], bl[1]);
                mma_f16(acc_lo[nf1], ah0, bl[2], bl[3]);
                mma_f16(acc_lo[nf0], al0, bh[0], bh[1]);
                mma_f16(acc_lo[nf1], al0, bh[2], bh[3]);
                mma_f16(acc_hh[4 + nf0], ah1, bh[0], bh[1]);
                mma_f16(acc_hh[4 + nf1], ah1, bh[2], bh[3]);
                mma_f16(acc_lo[4 + nf0], ah1, bl[0], bl[1]);
                mma_f16(acc_lo[4 + nf1], ah1, bl[2], bl[3]);
                mma_f16(acc_lo[4 + nf0], al1, bh[0], bh[1]);
                mma_f16(acc_lo[4 + nf1], al1, bh[2], bh[3]);
            }
        }

        if (ch == 7) {
            int k0 = (q >> 3) * 128;
#pragma unroll
            for (int mt = 0; mt < 2; mt++)
#pragma unroll
            for (int nf = 0; nf < 4; nf++) {
                int f = mt * 4 + nf;
                int ka = k0 + wr * 32 + nf * 8 + 2 * t;
                float e2a = e2s[ka], e2b = e2s[ka + 1];
                float dot0 = fmaf(acc_lo[f][0], INV2048, acc_hh[f][0]);
                float dot1 = fmaf(acc_lo[f][1], INV2048, acc_hh[f][1]);
                float dot2 = fmaf(acc_lo[f][2], INV2048, acc_hh[f][2]);
                float dot3 = fmaf(acc_lo[f][3], INV2048, acc_hh[f][3]);
                int ia = mt * 2, ib = mt * 2 + 1;
                float d0 = (e2a + z2r[ia]) - 2.0f * dot0;
                float d1 = (e2b + z2r[ia]) - 2.0f * dot1;
                float d2 = (e2a + z2r[ib]) - 2.0f * dot2;
                float d3 = (e2b + z2r[ib]) - 2.0f * dot3;
                if (d0 < bv[ia] || (d0 == bv[ia] && ka     < bk[ia])) { bv[ia] = d0; bk[ia] = ka; }
                if (d1 < bv[ia] || (d1 == bv[ia] && ka + 1 < bk[ia])) { bv[ia] = d1; bk[ia] = ka + 1; }
                if (d2 < bv[ib] || (d2 == bv[ib] && ka     < bk[ib])) { bv[ib] = d2; bk[ib] = ka; }
                if (d3 < bv[ib] || (d3 == bv[ib] && ka + 1 < bk[ib])) { bv[ib] = d3; bk[ib] = ka + 1; }
            }
        }

        if (q + 1 < 64) cp_wait0();            // this thread's copies landed
        asm volatile("bar.sync %0, 128;" :: "r"(wr + 1) : "memory");  // group-wide visibility
    }

#pragma unroll
    for (int i = 0; i < 4; i++) {
#pragma unroll
        for (int off = 1; off <= 2; off <<= 1) {
            float ov = __shfl_xor_sync(0xFFFFFFFFu, bv[i], off);
            int   ok = __shfl_xor_sync(0xFFFFFFFFu, bk[i], off);
            if (ov < bv[i] || (ov == bv[i] && ok < bk[i])) { bv[i] = ov; bk[i] = ok; }
        }
    }

    float* rval = (float*)smu;            // [4 wr][128 rows]
    int*   ridx = (int*)(smu + 512);
    __syncthreads();
    if (t == 0) {
#pragma unroll
        for (int mt = 0; mt < 2; mt++)
#pragma unroll
            for (int r8 = 0; r8 < 2; r8++) {
                int row = wp * 32 + mt * 16 + g + r8 * 8;
                rval[wr * 128 + row] = bv[mt * 2 + r8];
                ridx[wr * 128 + row] = bk[mt * 2 + r8];
            }
    }
    __syncthreads();
    if (tid < 128) {
        float bvv = rval[tid];
        int   bkk = ridx[tid];
#pragma unroll
        for (int r = 1; r < 4; r++) {
            float v = rval[r * 128 + tid];
            int   k2 = ridx[r * 128 + tid];
            if (v < bvv || (v == bvv && k2 < bkk)) { bvv = v; bkk = k2; }
        }
        int n = n0 + tid;
        g_idx[b * NN + n] = bkk;
        long long off = (long long)ZQ_SIZE + b * NN + n;
        if (off < (long long)out_size) dout[off] = (float)bkk;
    }
}

// ---------- kernel 5: gather z_q (STE-exact), loss partials ----------
__global__ void k_gather(const float* __restrict__ z, const float* __restrict__ E,
                         float* __restrict__ dout) {
    __shared__ float srow[32 * 257];
    __shared__ int   skid[32];
    __shared__ float sw[8];
    int b = blockIdx.x >> 5, h = blockIdx.x & 31;
    int tid = threadIdx.x;
    int warp = tid >> 5, lane = tid & 31;

    if (tid < 32) skid[tid] = g_idx[b * NN + h * WW + tid];
    __syncthreads();

#pragma unroll
    for (int r2 = 0; r2 < 4; r2++) {
        int r = warp * 4 + r2;
        const float* er = E + skid[r] * CC;
#pragma unroll
        for (int i = 0; i < 8; i++)
            srow[r * 257 + lane + 32 * i] = er[lane + 32 * i];
    }
    __syncthreads();

    int w = lane;
    float local = 0.f;
#pragma unroll 4
    for (int s = 0; s < 32; s++) {
        int c = warp * 32 + s;
        long long zoff = ((long long)(b * CC + c) * HH + h) * WW + w;
        float zv = z[zoff];
        float eq = srow[w * 257 + c];
        float d = eq - zv;
        local = fmaf(d, d, local);
        dout[zoff] = zv + (eq - zv);   // exact straight-through arithmetic
    }
#pragma unroll
    for (int o = 16; o; o >>= 1) local += __shfl_xor_sync(0xFFFFFFFFu, local, o);
    if (lane == 0) sw[warp] = local;
    __syncthreads();
    if (tid == 0) {
        float s2 = 0.f;
#pragma unroll
        for (int i = 0; i < 8; i++) s2 += sw[i];
        g_losspart[blockIdx.x] = s2;
    }
}

// ---------- kernel 6: deterministic loss finalize ----------
__global__ void k_final(float* __restrict__ dout, int out_size) {
    __shared__ float smf[256];
    float s = 0.f;
    for (int i = threadIdx.x; i < 1024; i += 256) s += g_losspart[i];
    smf[threadIdx.x] = s;
    __syncthreads();
    if (threadIdx.x == 0) {
        float t = 0.f;
        for (int i = 0; i < 256; i++) t += smf[i];
        float m = t / 8388608.0f;
        float loss = m + 0.25f * m;
        long long off = (long long)ZQ_SIZE + IDX_SIZE;
        if (off < (long long)out_size) dout[off] = loss;
    }
}

extern "C" void kernel_launch(void* const* d_in, const int* in_sizes, int n_in,
                              void* d_out, int out_size) {
    const float* z = (const float*)d_in[0];
    const float* E = (const float*)d_in[1];
    float* out = (float*)d_out;

    cudaFuncSetAttribute(k_mma, cudaFuncAttributeMaxDynamicSharedMemorySize, SMEM_MMA_BYTES);

    k_e2<<<128, 256>>>(E);
    k_tr<<<1024, 256>>>(z);
    k_z2<<<128, 256>>>();
    k_mma<<<256, 512, SMEM_MMA_BYTES>>>(out, out_size);
    if (out_size >= ZQ_SIZE) k_gather<<<1024, 256>>>(z, E, out);
    k_final<<<1, 256>>>(out, out_size);
}